// round 15
// baseline (speedup 1.0000x reference)
#include <cuda_runtime.h>
#include <stdint.h>

#define GH 52
#define GW 52
#define NB 5
#define NCELL (GH*GW)              // 2704
#define NBOX 13520                 // 52*52*5
#define NFLT  (NCELL*25)           // 67600 input floats
#define ROWBITS 288                // padded positions per grid row (260 used)
#define PWORDS 468
#define PPOS   (PWORDS*32)         // 14976 padded positions
#define IOU_T  0.4f
#define STK    80
#define M48    0x0000FFFFFFFFFFFFull

// Per-position record (padded layout), one 64-bit word:
//   bits [0:16)  pred mask row dy=-1 (15 bits, bit (dx+1)*5+bb)
//   bits[16:32)  pred mask row dy= 0
//   bits[32:48)  pred mask row dy=+1
//   bits[48:64)  memo state: 0=unknown, 1=kept, 2=suppressed
// Padding positions are never written and stay zero.
__device__ ushort4 g_pm[PPOS];

// ---------------------------------------------------------------------------
// Vectorized 25-float cell load: align-down to 16B, 7x float4, constant-index
// extract per (base & 3). Scalar fallback for the tail cell (over-read guard).
// ---------------------------------------------------------------------------
__device__ __forceinline__ void load25(const float* __restrict__ x, int base,
                                       float* v)
{
    if (base + 28 <= NFLT) {
        int off = base & 3;
        const float4* p = (const float4*)(x + (base & ~3));
        float b[28];
        #pragma unroll
        for (int k = 0; k < 7; k++) {
            float4 f = __ldg(&p[k]);
            b[4*k+0] = f.x; b[4*k+1] = f.y; b[4*k+2] = f.z; b[4*k+3] = f.w;
        }
        switch (off) {
        case 0: {
            #pragma unroll
            for (int k = 0; k < 25; k++) v[k] = b[k];
        } break;
        case 1: {
            #pragma unroll
            for (int k = 0; k < 25; k++) v[k] = b[k+1];
        } break;
        case 2: {
            #pragma unroll
            for (int k = 0; k < 25; k++) v[k] = b[k+2];
        } break;
        default: {
            #pragma unroll
            for (int k = 0; k < 25; k++) v[k] = b[k+3];
        } break;
        }
    } else {
        #pragma unroll
        for (int k = 0; k < 25; k++) v[k] = __ldg(&x[base + k]);
    }
}

// ---------------------------------------------------------------------------
// Kernel 1: decode + predecessor masks. One thread per (cell, dyRow).
// The 5 boxes of a cell share all neighbor data; neighbor geometry is
// decoded once per neighbor box (identical fp32 subexpressions, just
// hoisted). Per-pair IoU op sequence is byte-identical to the proven one.
// ---------------------------------------------------------------------------
__global__ void __launch_bounds__(256)
decode_kernel(const float* __restrict__ x, float* __restrict__ out)
{
    int id = blockIdx.x * blockDim.x + threadIdx.x;
    if (id >= 3 * NCELL) return;
    int dyI  = id / NCELL;          // 0,1,2 -> dy = dyI-1
    int cell = id - dyI * NCELL;
    int gy   = cell / GW;
    int gx   = cell - gy * GW;

    const float sx = 416.0f / GW;   // 8
    const float sy = 416.0f / GH;   // 8

    // ---- decode own 5 boxes ----
    float v[25];
    load25(x, cell * 25, v);

    float jx1[NB], jy1[NB], jx2[NB], jy2[NB], aj[NB], sj[NB];
    #pragma unroll
    for (int bb = 0; bb < NB; bb++) {
        float c0 = v[bb*5+0], c1 = v[bb*5+1], c2 = v[bb*5+2], c3 = v[bb*5+3];
        sj[bb] = v[bb*5+4];
        float cx = (c0 + (float)gx) * sx;
        float w  = c2 * sx;
        float cy = (c1 + (float)gy) * sy;
        float h  = c3 * sy;
        cy = 416.0f - cy;
        jx1[bb] = cx - w * 0.5f; jy1[bb] = cy - h * 0.5f;
        jx2[bb] = cx + w * 0.5f; jy2[bb] = cy + h * 0.5f;
        aj[bb]  = fmaxf(jx2[bb] - jx1[bb], 0.0f) * fmaxf(jy2[bb] - jy1[bb], 0.0f);
    }

    int pos0 = gy * ROWBITS + gx * 5;

    if (dyI == 1) {
        // out boxes + memo reset for the cell's 5 boxes
        float* o = out + cell * 25;
        #pragma unroll
        for (int bb = 0; bb < NB; bb++) {
            o[bb*5+0] = jx1[bb]; o[bb*5+1] = jy1[bb];
            o[bb*5+2] = jx2[bb]; o[bb*5+3] = jy2[bb];
            ((unsigned short*)&g_pm[pos0 + bb])[3] = 0;
            // o[bb*5+4] written by resolve_kernel.
        }
    }

    unsigned m[NB] = {0, 0, 0, 0, 0};
    int ny = gy + dyI - 1;
    if ((unsigned)ny < GH) {
        #pragma unroll
        for (int dxi = 0; dxi < 3; dxi++) {
            int nx = gx + dxi - 1;
            if ((unsigned)nx >= GW) continue;
            int ncell = ny * GW + nx;
            float q[25];
            load25(x, ncell * 25, q);

            #pragma unroll
            for (int nb = 0; nb < NB; nb++) {
                int i = ncell * NB + nb;
                float si = q[nb*5+4];
                float d0 = q[nb*5+0], d1 = q[nb*5+1];
                float d2 = q[nb*5+2], d3 = q[nb*5+3];
                float icx = (d0 + (float)nx) * sx;
                float iw_ = d2 * sx;
                float icy = (d1 + (float)ny) * sy;
                float ih_ = d3 * sy;
                icy = 416.0f - icy;
                float ix1 = icx - iw_ * 0.5f, iy1 = icy - ih_ * 0.5f;
                float ix2 = icx + iw_ * 0.5f, iy2 = icy + ih_ * 0.5f;
                float ai  = fmaxf(ix2 - ix1, 0.0f) * fmaxf(iy2 - iy1, 0.0f);

                #pragma unroll
                for (int jb = 0; jb < NB; jb++) {
                    int j = cell * NB + jb;
                    bool higher = (si > sj[jb]) || (si == sj[jb] && i < j);
                    float iw = fmaxf(fminf(ix2, jx2[jb]) - fmaxf(ix1, jx1[jb]), 0.0f);
                    float ih = fmaxf(fminf(iy2, jy2[jb]) - fmaxf(iy1, jy1[jb]), 0.0f);
                    float inter = iw * ih;
                    float uni = ai + aj[jb] - inter;
                    float iou = (uni > 0.0f) ? inter / fmaxf(uni, 1e-12f) : 0.0f;
                    bool on = (iou > IOU_T) && higher && (i != j);
                    m[jb] |= (on ? 1u : 0u) << (dxi * 5 + nb);
                }
            }
        }
    }
    #pragma unroll
    for (int bb = 0; bb < NB; bb++)
        ((unsigned short*)&g_pm[pos0 + bb])[dyI] = (unsigned short)m[bb];
}

// ---------------------------------------------------------------------------
// Kernel 2: per-box memoized DFS with 2-wide sibling prefetch (R14 version,
// unchanged). One thread per box, no barriers. Stale L1 reads are safe:
// state is monotone 0 -> {1,2} with deterministic final value; a stale 0
// only causes recomputation. Well-founded recursion => termination; unique
// fixpoint == exact greedy NMS.
// ---------------------------------------------------------------------------
__device__ __forceinline__ void set_state(int pos, unsigned short v)
{
    ((unsigned short*)&g_pm[pos])[3] = v;
}

__device__ __forceinline__ int bb_of(int q)
{
    int bb = q - (q >= 5 ? 5 : 0);
    return bb - (bb >= 5 ? 5 : 0);
}

__global__ void __launch_bounds__(256)
resolve_kernel(const float* __restrict__ x, float* __restrict__ out)
{
    int j = blockIdx.x * blockDim.x + threadIdx.x;
    if (j >= NBOX) return;
    int row = j / 260;
    int rem = j - row * 260;
    int pos = row * ROWBITS + rem;

    const uint64_t* gm = (const uint64_t*)g_pm;

    uint64_t w0 = gm[pos];
    int res = (int)(w0 >> 48);
    if (res == 0) {
        if ((w0 & M48) == 0ull) {
            res = 1;
            set_state(pos, 1);
        } else {
            int      fpos[STK], fpb[STK];
            uint64_t frem[STK];
            fpos[0] = pos;
            fpb[0]  = pos - (rem % 5) - ROWBITS - 5;
            frem[0] = w0 & M48;
            int sp = 1;
            while (sp > 0) {
                uint64_t r = frem[sp - 1];
                int fin = 0;
                if (r == 0ull) {
                    fin = 1;                           // no kept pred -> kept
                } else {
                    int pb = fpb[sp - 1];
                    int k0 = __ffsll((long long)r) - 1;
                    uint64_t r1 = r & (r - 1);
                    int q0    = k0 & 15;
                    int pred0 = pb + (k0 >> 4) * ROWBITS + q0;
                    uint64_t wp0 = gm[pred0];
                    int pred1 = -1;
                    uint64_t wp1 = 0, r2 = r1;
                    if (r1) {
                        int k1 = __ffsll((long long)r1) - 1;
                        r2 = r1 & (r1 - 1);
                        int q1 = k1 & 15;
                        pred1 = pb + (k1 >> 4) * ROWBITS + q1;
                        wp1 = gm[pred1];
                    }

                    frem[sp - 1] = r1;
                    int sv0 = (int)(wp0 >> 48);
                    if (sv0 == 1) {
                        fin = 2;
                    } else if (sv0 == 0) {
                        uint64_t m0 = wp0 & M48;
                        if (m0 == 0ull) {
                            set_state(pred0, 1);
                            fin = 2;
                        } else if (sp < STK) {
                            fpos[sp] = pred0;
                            fpb[sp]  = pred0 - bb_of(q0) - ROWBITS - 5;
                            frem[sp] = m0;
                            sp++;
                            continue;
                        } else {
                            volatile unsigned short* vs =
                                &((unsigned short*)&g_pm[pred0])[3];
                            unsigned short vv;
                            do { vv = *vs; } while (vv == 0);
                            if (vv == 1) fin = 2;
                        }
                    }
                    if (!fin && pred1 >= 0) {
                        frem[sp - 1] = r2;
                        int sv1 = (int)(wp1 >> 48);
                        if (sv1 == 1) {
                            fin = 2;
                        } else if (sv1 == 0) {
                            uint64_t m1 = wp1 & M48;
                            if (m1 == 0ull) {
                                set_state(pred1, 1);
                                fin = 2;
                            } else if (sp < STK) {
                                int q1b = pred1 % ROWBITS;
                                fpos[sp] = pred1;
                                fpb[sp]  = pred1 - (q1b % 5) - ROWBITS - 5;
                                frem[sp] = m1;
                                sp++;
                                continue;
                            } else {
                                volatile unsigned short* vs =
                                    &((unsigned short*)&g_pm[pred1])[3];
                                unsigned short vv;
                                do { vv = *vs; } while (vv == 0);
                                if (vv == 1) fin = 2;
                            }
                        }
                    }
                    if (!fin && frem[sp - 1] == 0ull) fin = 1;
                    if (!fin) continue;
                }
                set_state(fpos[sp - 1], (unsigned short)fin);
                sp--;
                if (sp == 0) {
                    res = fin;
                } else if (fin == 1) {
                    set_state(fpos[sp - 1], 2);
                    sp--;
                    if (sp == 0) res = 2;
                }
            }
        }
    }

    out[j * 5 + 4] = (res == 1) ? __ldg(&x[j * 5 + 4]) : 0.0f;
}

// ---------------------------------------------------------------------------
extern "C" void kernel_launch(void* const* d_in, const int* in_sizes, int n_in,
                              void* d_out, int out_size)
{
    const float* x   = (const float*)d_in[0];
    float*       out = (float*)d_out;

    decode_kernel<<<(3 * NCELL + 255) / 256, 256>>>(x, out);   // 32 blocks
    resolve_kernel<<<(NBOX + 255) / 256, 256>>>(x, out);
}

// round 16
// speedup vs baseline: 2.2328x; 2.2328x over previous
#include <cuda_runtime.h>
#include <stdint.h>

#define GH 52
#define GW 52
#define NB 5
#define NBOX 13520                 // 52*52*5
#define ROWBITS 288                // padded positions per grid row (260 used)
#define PWORDS 468
#define PPOS   (PWORDS*32)         // 14976 padded positions
#define IOU_T  0.4f
#define STK    80
#define M48    0x0000FFFFFFFFFFFFull

// Per-position record (padded layout), one 64-bit word:
//   bits [0:16)  pred mask row dy=-1 (15 bits, bit (dx+1)*5+bb)
//   bits[16:32)  pred mask row dy= 0
//   bits[32:48)  pred mask row dy=+1
//   bits[48:64)  memo state: 0=unknown, 1=kept, 2=suppressed
// Padding positions are never written and stay zero.
__device__ ushort4 g_pm[PPOS];

// ---------------------------------------------------------------------------
// Kernel 1: decode + predecessor masks (R12 version — fastest measured).
// One thread per (box, dyRow); branchless q[25] cell preload. Identical
// fp32 op sequence as the reference decode (rel_err 0.0 across all rounds).
// ---------------------------------------------------------------------------
__global__ void decode_kernel(const float* __restrict__ x, float* __restrict__ out)
{
    int id = blockIdx.x * blockDim.x + threadIdx.x;
    if (id >= 3 * NBOX) return;
    int dyI = id / NBOX;            // 0,1,2 -> dy = dyI-1
    int j   = id - dyI * NBOX;

    int cell = j / NB;
    int b    = j - cell * NB;
    int gy   = cell / GW;
    int gx   = cell - gy * GW;

    const float sx = 416.0f / GW;   // 8
    const float sy = 416.0f / GH;   // 8

    const float* p = x + j * 5;
    float c0 = p[0], c1 = p[1], c2 = p[2], c3 = p[3], sj = p[4];

    float cx = (c0 + (float)gx) * sx;
    float w  = c2 * sx;
    float cy = (c1 + (float)gy) * sy;
    float h  = c3 * sy;
    cy = 416.0f - cy;
    float jx1 = cx - w * 0.5f, jy1 = cy - h * 0.5f;
    float jx2 = cx + w * 0.5f, jy2 = cy + h * 0.5f;

    int pos = gy * ROWBITS + gx * 5 + b;

    if (dyI == 1) {
        float* o = out + j * 5;
        o[0] = jx1; o[1] = jy1; o[2] = jx2; o[3] = jy2;
        ((unsigned short*)&g_pm[pos])[3] = 0;   // memo reset (replay-safe)
        // o[4] written by resolve_kernel.
    }

    float aj = fmaxf(jx2 - jx1, 0.0f) * fmaxf(jy2 - jy1, 0.0f);

    unsigned mask = 0;
    int ny = gy + dyI - 1;
    if ((unsigned)ny < GH) {
        #pragma unroll
        for (int dxi = 0; dxi < 3; dxi++) {
            int nx = gx + dxi - 1;
            if ((unsigned)nx >= GW) continue;
            int ncell = ny * GW + nx;
            const float* cp = x + ncell * 25;
            float q[25];
            #pragma unroll
            for (int k = 0; k < 25; k++) q[k] = cp[k];

            #pragma unroll
            for (int bb = 0; bb < NB; bb++) {
                int i = ncell * NB + bb;
                float si = q[bb * 5 + 4];
                bool higher = (si > sj) || (si == sj && i < j);
                float d0 = q[bb * 5 + 0], d1 = q[bb * 5 + 1];
                float d2 = q[bb * 5 + 2], d3 = q[bb * 5 + 3];
                float icx = (d0 + (float)nx) * sx;
                float iw_ = d2 * sx;
                float icy = (d1 + (float)ny) * sy;
                float ih_ = d3 * sy;
                icy = 416.0f - icy;
                float ix1 = icx - iw_ * 0.5f, iy1 = icy - ih_ * 0.5f;
                float ix2 = icx + iw_ * 0.5f, iy2 = icy + ih_ * 0.5f;

                float iw = fmaxf(fminf(ix2, jx2) - fmaxf(ix1, jx1), 0.0f);
                float ih = fmaxf(fminf(iy2, jy2) - fmaxf(iy1, jy1), 0.0f);
                float inter = iw * ih;
                float ai  = fmaxf(ix2 - ix1, 0.0f) * fmaxf(iy2 - iy1, 0.0f);
                float uni = ai + aj - inter;
                float iou = (uni > 0.0f) ? inter / fmaxf(uni, 1e-12f) : 0.0f;
                bool on = (iou > IOU_T) && higher && (i != j);
                mask |= (on ? 1u : 0u) << (dxi * 5 + bb);
            }
        }
    }
    ((unsigned short*)&g_pm[pos])[dyI] = (unsigned short)mask;
}

// ---------------------------------------------------------------------------
// Kernel 2: per-box memoized DFS with 2-wide sibling prefetch (R14 version),
// launched 128x106 for double SM coverage. One thread per box, no barriers.
// Stale L1 reads are safe: state is monotone 0 -> {1,2} with deterministic
// final value; a stale 0 only causes recomputation. Well-founded recursion
// => termination; unique fixpoint == exact greedy NMS.
// Addressing: bit k -> pred = pbase + (k>>4)*ROWBITS + (k&15),
// pbase = pos - bb - ROWBITS - 5.
// ---------------------------------------------------------------------------
__device__ __forceinline__ void set_state(int pos, unsigned short v)
{
    ((unsigned short*)&g_pm[pos])[3] = v;
}

__device__ __forceinline__ int bb_of(int q)
{
    int bb = q - (q >= 5 ? 5 : 0);
    return bb - (bb >= 5 ? 5 : 0);
}

__global__ void __launch_bounds__(128)
resolve_kernel(const float* __restrict__ x, float* __restrict__ out)
{
    int j = blockIdx.x * blockDim.x + threadIdx.x;
    if (j >= NBOX) return;
    int row = j / 260;
    int rem = j - row * 260;
    int pos = row * ROWBITS + rem;

    const uint64_t* gm = (const uint64_t*)g_pm;

    uint64_t w0 = gm[pos];
    int res = (int)(w0 >> 48);
    if (res == 0) {
        if ((w0 & M48) == 0ull) {
            res = 1;
            set_state(pos, 1);
        } else {
            int      fpos[STK], fpb[STK];
            uint64_t frem[STK];
            fpos[0] = pos;
            fpb[0]  = pos - (rem % 5) - ROWBITS - 5;
            frem[0] = w0 & M48;
            int sp = 1;
            while (sp > 0) {
                uint64_t r = frem[sp - 1];
                int fin = 0;
                if (r == 0ull) {
                    fin = 1;                           // no kept pred -> kept
                } else {
                    int pb = fpb[sp - 1];
                    // extract up to 2 sibling preds, issue both loads (MLP)
                    int k0 = __ffsll((long long)r) - 1;
                    uint64_t r1 = r & (r - 1);
                    int q0    = k0 & 15;
                    int pred0 = pb + (k0 >> 4) * ROWBITS + q0;
                    uint64_t wp0 = gm[pred0];
                    int pred1 = -1;
                    uint64_t wp1 = 0, r2 = r1;
                    if (r1) {
                        int k1 = __ffsll((long long)r1) - 1;
                        r2 = r1 & (r1 - 1);
                        int q1 = k1 & 15;
                        pred1 = pb + (k1 >> 4) * ROWBITS + q1;
                        wp1 = gm[pred1];
                    }

                    // ---- consume pred0 ----
                    frem[sp - 1] = r1;
                    int sv0 = (int)(wp0 >> 48);
                    if (sv0 == 1) {
                        fin = 2;
                    } else if (sv0 == 0) {
                        uint64_t m0 = wp0 & M48;
                        if (m0 == 0ull) {
                            set_state(pred0, 1);
                            fin = 2;
                        } else if (sp < STK) {
                            fpos[sp] = pred0;
                            fpb[sp]  = pred0 - bb_of(q0) - ROWBITS - 5;
                            frem[sp] = m0;
                            sp++;
                            continue;                  // descend (wp1 unused)
                        } else {
                            volatile unsigned short* vs =
                                &((unsigned short*)&g_pm[pred0])[3];
                            unsigned short vv;
                            do { vv = *vs; } while (vv == 0);
                            if (vv == 1) fin = 2;
                        }
                    }
                    // sv0 == 2 (or resolved above): consume pred1 if loaded
                    if (!fin && pred1 >= 0) {
                        frem[sp - 1] = r2;
                        int sv1 = (int)(wp1 >> 48);
                        if (sv1 == 1) {
                            fin = 2;
                        } else if (sv1 == 0) {
                            uint64_t m1 = wp1 & M48;
                            if (m1 == 0ull) {
                                set_state(pred1, 1);
                                fin = 2;
                            } else if (sp < STK) {
                                int q1b = pred1 % ROWBITS;
                                fpos[sp] = pred1;
                                fpb[sp]  = pred1 - (q1b % 5) - ROWBITS - 5;
                                frem[sp] = m1;
                                sp++;
                                continue;              // descend
                            } else {
                                volatile unsigned short* vs =
                                    &((unsigned short*)&g_pm[pred1])[3];
                                unsigned short vv;
                                do { vv = *vs; } while (vv == 0);
                                if (vv == 1) fin = 2;
                            }
                        }
                        // sv1 == 2: both suppressed, loop continues
                    }
                    if (!fin && frem[sp - 1] == 0ull) fin = 1;
                    if (!fin) continue;                // more siblings to scan
                }
                // ---- pop / propagate ----
                set_state(fpos[sp - 1], (unsigned short)fin);
                sp--;
                if (sp == 0) {
                    res = fin;
                } else if (fin == 1) {                 // kept child -> parent supp
                    set_state(fpos[sp - 1], 2);
                    sp--;
                    if (sp == 0) res = 2;
                }
            }
        }
    }

    out[j * 5 + 4] = (res == 1) ? __ldg(&x[j * 5 + 4]) : 0.0f;
}

// ---------------------------------------------------------------------------
extern "C" void kernel_launch(void* const* d_in, const int* in_sizes, int n_in,
                              void* d_out, int out_size)
{
    const float* x   = (const float*)d_in[0];
    float*       out = (float*)d_out;

    decode_kernel<<<(3 * NBOX + 255) / 256, 256>>>(x, out);   // 159 blocks
    resolve_kernel<<<(NBOX + 127) / 128, 128>>>(x, out);      // 106 blocks
}